// round 12
// baseline (speedup 1.0000x reference)
#include <cuda_runtime.h>

#define NB 64
#define LQ 256
#define EE 64
#define HH 64

// Scratch (static __device__ — no allocations allowed)
__device__ float g_vt[NB * LQ * EE];    // vt[n][l][k] = values[k][l][n]   (4 MB)
__device__ float g_attn[NB * EE * EE];  // attn[n][a][b]                   (1 MB)
__device__ float g_M[NB * EE * EE];     // M[n][e][k] = (W @ A_n)[e][k]    (1 MB)

// ---------------------------------------------------------------------------
// K_front: merged launch.
//   blocks [0,128):   energy Q·K^T + softmax -> g_attn  (n, half) [long pole]
//   blocks [128,384): transpose values[k][l][n] -> vt[n][l][k]  (one per l)
// Attn phase: register prefetch of next chunk + 2x lp-unroll with dual
// accumulator sets (16 independent FMA chains) to cover FFMA latency.
// ---------------------------------------------------------------------------
__global__ void __launch_bounds__(256) k_front(const float* __restrict__ values,
                                               const float* __restrict__ query,
                                               const float* __restrict__ keys) {
    __shared__ float sh[5248];           // aliased pool (max of both phases)
    const int tid = threadIdx.x;

    if (blockIdx.x >= 128) {
        // ---- transpose phase ----
        float (*tile)[65] = (float(*)[65])sh;
        const int l = blockIdx.x - 128;
#pragma unroll
        for (int i = 0; i < 4; i++) {
            int f = i * 256 + tid;          // float4 index 0..1023
            int k = f >> 4;                 // 0..63
            int n4 = f & 15;                // 0..15
            float4 v = *(const float4*)(values + ((k * LQ + l) * EE) + n4 * 4);
            tile[k][n4 * 4 + 0] = v.x;
            tile[k][n4 * 4 + 1] = v.y;
            tile[k][n4 * 4 + 2] = v.z;
            tile[k][n4 * 4 + 3] = v.w;
        }
        __syncthreads();
#pragma unroll
        for (int i = 0; i < 4; i++) {
            int f = i * 256 + tid;
            int nn = f >> 4;
            int k4 = f & 15;
            float4 v = make_float4(tile[k4 * 4 + 0][nn], tile[k4 * 4 + 1][nn],
                                   tile[k4 * 4 + 2][nn], tile[k4 * 4 + 3][nn]);
            *(float4*)(g_vt + ((nn * LQ + l) * EE) + k4 * 4) = v;
        }
        return;
    }

    // ---- attention phase ----
    const int n = blockIdx.x >> 1;
    const int half = blockIdx.x & 1;
    float (*sQ)[32] = (float(*)[32])sh;            // [l'][a_local]  1024
    float (*sK)[64] = (float(*)[64])(sh + 1024);   // [l'][b]        2048
    float (*sE)[68] = (float(*)[68])(sh + 3072);   // energy         2176
    const int a0 = (tid >> 4) * 2;  // 0..30 step 2
    const int b0 = (tid & 15) * 4;  // 0..60 step 4

    // per-thread load slots
    const int qlp = tid >> 3;        // 0..31 (Q row)
    const int qc = (tid & 7) * 4;    // 0..28 (Q col*4)
    const int klp0 = tid >> 4;       // 0..15 (K rows: tid and tid+256)
    const int kc = (tid & 15) * 4;   // 0..60

    // dual accumulator sets (even/odd lp) -> 16 independent FMA chains
    float a00 = 0.f, a01 = 0.f, a02 = 0.f, a03 = 0.f;
    float a10 = 0.f, a11 = 0.f, a12 = 0.f, a13 = 0.f;
    float c00 = 0.f, c01 = 0.f, c02 = 0.f, c03 = 0.f;
    float c10 = 0.f, c11 = 0.f, c12 = 0.f, c13 = 0.f;

    // prefetch chunk 0
    float4 qreg = *(const float4*)(query + ((n * LQ + qlp) * EE) + half * 32 + qc);
    float4 kreg0 = *(const float4*)(keys + ((n * LQ + klp0) * EE) + kc);
    float4 kreg1 = *(const float4*)(keys + ((n * LQ + 16 + klp0) * EE) + kc);

    for (int c = 0; c < 8; c++) {
        *(float4*)&sQ[qlp][qc] = qreg;
        *(float4*)&sK[klp0][kc] = kreg0;
        *(float4*)&sK[16 + klp0][kc] = kreg1;
        __syncthreads();

        if (c < 7) {
            const int l0 = (c + 1) * 32;
            qreg = *(const float4*)(query + ((n * LQ + l0 + qlp) * EE) + half * 32 + qc);
            kreg0 = *(const float4*)(keys + ((n * LQ + l0 + klp0) * EE) + kc);
            kreg1 = *(const float4*)(keys + ((n * LQ + l0 + 16 + klp0) * EE) + kc);
        }

#pragma unroll
        for (int lp = 0; lp < 32; lp += 2) {
            float2 qv0 = *(const float2*)&sQ[lp][a0];
            float4 kv0 = *(const float4*)&sK[lp][b0];
            float2 qv1 = *(const float2*)&sQ[lp + 1][a0];
            float4 kv1 = *(const float4*)&sK[lp + 1][b0];
            a00 += qv0.x * kv0.x; a01 += qv0.x * kv0.y; a02 += qv0.x * kv0.z; a03 += qv0.x * kv0.w;
            a10 += qv0.y * kv0.x; a11 += qv0.y * kv0.y; a12 += qv0.y * kv0.z; a13 += qv0.y * kv0.w;
            c00 += qv1.x * kv1.x; c01 += qv1.x * kv1.y; c02 += qv1.x * kv1.z; c03 += qv1.x * kv1.w;
            c10 += qv1.y * kv1.x; c11 += qv1.y * kv1.y; c12 += qv1.y * kv1.z; c13 += qv1.y * kv1.w;
        }
        __syncthreads();
    }
    a00 += c00; a01 += c01; a02 += c02; a03 += c03;
    a10 += c10; a11 += c11; a12 += c12; a13 += c13;
    *(float4*)&sE[a0][b0]     = make_float4(a00, a01, a02, a03);
    *(float4*)&sE[a0 + 1][b0] = make_float4(a10, a11, a12, a13);
    __syncthreads();

    // softmax: 8 warps x 4 rows each (32 rows in this half); hd=1 so no scale
    const int w = tid >> 5, lane = tid & 31;
#pragma unroll
    for (int r = 0; r < 4; r++) {
        int row = w * 4 + r;
        float v0 = sE[row][lane];
        float v1 = sE[row][lane + 32];
        float m = fmaxf(v0, v1);
#pragma unroll
        for (int off = 16; off; off >>= 1) m = fmaxf(m, __shfl_xor_sync(0xffffffffu, m, off));
        float e0 = __expf(v0 - m);
        float e1 = __expf(v1 - m);
        float s = e0 + e1;
#pragma unroll
        for (int off = 16; off; off >>= 1) s += __shfl_xor_sync(0xffffffffu, s, off);
        float inv = 1.0f / s;
        float* dst = g_attn + (n * EE + half * 32 + row) * EE;
        dst[lane] = e0 * inv;
        dst[lane + 32] = e1 * inv;
    }
}

// ---------------------------------------------------------------------------
// K2: M_n[e][k] = sum_e' W[e][e'] * attn[n][e'][k]   (fold fc into attn)
// grid: 64 blocks (one per n)
// ---------------------------------------------------------------------------
__global__ void __launch_bounds__(256) k_M(const float* __restrict__ W) {
    const int n = blockIdx.x;
    __shared__ float sWt[64][68];  // sWt[e'][e] = W[e][e']
    __shared__ float sA[64][68];   // sA[e'][k]
    const int tid = threadIdx.x;
#pragma unroll
    for (int i = 0; i < 16; i++) {
        int idx = i * 256 + tid;
        int r = idx >> 6, c = idx & 63;
        sWt[c][r] = W[idx];                       // transpose W on the fly
        sA[r][c] = g_attn[n * 4096 + idx];
    }
    __syncthreads();
    const int e0 = (tid >> 4) * 4;
    const int k0 = (tid & 15) * 4;
    float acc[4][4] = {};
#pragma unroll
    for (int ep = 0; ep < 64; ep++) {
        float4 wv = *(const float4*)&sWt[ep][e0];
        float4 av = *(const float4*)&sA[ep][k0];
        acc[0][0] += wv.x * av.x; acc[0][1] += wv.x * av.y; acc[0][2] += wv.x * av.z; acc[0][3] += wv.x * av.w;
        acc[1][0] += wv.y * av.x; acc[1][1] += wv.y * av.y; acc[1][2] += wv.y * av.z; acc[1][3] += wv.y * av.w;
        acc[2][0] += wv.z * av.x; acc[2][1] += wv.z * av.y; acc[2][2] += wv.z * av.z; acc[2][3] += wv.z * av.w;
        acc[3][0] += wv.w * av.x; acc[3][1] += wv.w * av.y; acc[3][2] += wv.w * av.z; acc[3][3] += wv.w * av.w;
    }
#pragma unroll
    for (int i = 0; i < 4; i++) {
        *(float4*)(g_M + ((n * 64 + e0 + i) * 64) + k0) =
            make_float4(acc[i][0], acc[i][1], acc[i][2], acc[i][3]);
    }
}

// ---------------------------------------------------------------------------
// K3: tiled GEMV + LayerNorm; writes ONLY the h=0 slice (4 MB).
// grid: 512 blocks = (n, 32-l chunk); 256 threads = (16 l-pairs) x (16 e-quads)
// ---------------------------------------------------------------------------
__global__ void __launch_bounds__(256) k_compute(const float* __restrict__ bias,
                                                 const float* __restrict__ lnw,
                                                 const float* __restrict__ lnb,
                                                 float* __restrict__ out) {
    const int n = blockIdx.x >> 3;
    const int lc = blockIdx.x & 7;
    const int tid = threadIdx.x;

    __shared__ float sMt[64][68];   // sMt[k][e] = M_n[e][k]
    __shared__ float sv[32][68];    // sv[l'][k]
    __shared__ float sy[32][64];    // normalized output tile
    __shared__ float sb[64], sw[64], sbeta[64];

    if (tid < 64) {
        sb[tid] = bias[tid];
        sw[tid] = lnw[tid];
        sbeta[tid] = lnb[tid];
    }

    // Load + transpose M_n (64x64) into sMt[k][e]
    const float* Mn = g_M + n * 4096;
#pragma unroll
    for (int i = 0; i < 16; i++) {
        int idx = i * 256 + tid;
        int e = idx >> 6, k = idx & 63;
        sMt[k][e] = Mn[idx];
    }
    // Load vt tile (32 x 64), coalesced
    const int lbase = lc * 32;
    const float* vtn = g_vt + (n * LQ + lbase) * EE;
#pragma unroll
    for (int i = 0; i < 8; i++) {
        int idx = i * 256 + tid;
        sv[idx >> 6][idx & 63] = vtn[idx];
    }
    __syncthreads();

    // Micro-tile: 2 l-rows x 4 e-cols per thread
    const int r0 = (tid >> 4) * 2;   // 0..30
    const int e0 = (tid & 15) * 4;   // 0..60

    float a00 = 0.f, a01 = 0.f, a02 = 0.f, a03 = 0.f;
    float a10 = 0.f, a11 = 0.f, a12 = 0.f, a13 = 0.f;
#pragma unroll
    for (int k = 0; k < 64; k++) {
        float v0 = sv[r0][k];
        float v1 = sv[r0 + 1][k];
        float4 m = *(const float4*)&sMt[k][e0];
        a00 += v0 * m.x; a01 += v0 * m.y; a02 += v0 * m.z; a03 += v0 * m.w;
        a10 += v1 * m.x; a11 += v1 * m.y; a12 += v1 * m.z; a13 += v1 * m.w;
    }
    // add fc bias before LN
    float b0v = sb[e0], b1v = sb[e0 + 1], b2v = sb[e0 + 2], b3v = sb[e0 + 3];
    a00 += b0v; a01 += b1v; a02 += b2v; a03 += b3v;
    a10 += b0v; a11 += b1v; a12 += b2v; a13 += b3v;

    // LN stats: reduce over the 16 lanes that share a row-pair (offsets 1..8)
    float s0 = (a00 + a01) + (a02 + a03);
    float q0 = (a00 * a00 + a01 * a01) + (a02 * a02 + a03 * a03);
    float s1 = (a10 + a11) + (a12 + a13);
    float q1 = (a10 * a10 + a11 * a11) + (a12 * a12 + a13 * a13);
#pragma unroll
    for (int off = 8; off; off >>= 1) {
        s0 += __shfl_xor_sync(0xffffffffu, s0, off);
        q0 += __shfl_xor_sync(0xffffffffu, q0, off);
        s1 += __shfl_xor_sync(0xffffffffu, s1, off);
        q1 += __shfl_xor_sync(0xffffffffu, q1, off);
    }
    float mu0 = s0 * (1.0f / 64.0f);
    float var0 = q0 * (1.0f / 64.0f) - mu0 * mu0;
    float ri0 = rsqrtf(var0 + 1e-5f);
    float mu1 = s1 * (1.0f / 64.0f);
    float var1 = q1 * (1.0f / 64.0f) - mu1 * mu1;
    float ri1 = rsqrtf(var1 + 1e-5f);

    float w0 = sw[e0], w1 = sw[e0 + 1], w2 = sw[e0 + 2], w3 = sw[e0 + 3];
    float g0 = sbeta[e0], g1 = sbeta[e0 + 1], g2 = sbeta[e0 + 2], g3 = sbeta[e0 + 3];

    *(float4*)&sy[r0][e0] = make_float4((a00 - mu0) * ri0 * w0 + g0,
                                        (a01 - mu0) * ri0 * w1 + g1,
                                        (a02 - mu0) * ri0 * w2 + g2,
                                        (a03 - mu0) * ri0 * w3 + g3);
    *(float4*)&sy[r0 + 1][e0] = make_float4((a10 - mu1) * ri1 * w0 + g0,
                                            (a11 - mu1) * ri1 * w1 + g1,
                                            (a12 - mu1) * ri1 * w2 + g2,
                                            (a13 - mu1) * ri1 * w3 + g3);
    __syncthreads();

    // write h = 0 slice only (coalesced STG.128)
    const float4* sy4 = (const float4*)sy;
    float4* dst = (float4*)out + n * 4096 + lc * 512 + tid;
    dst[0] = sy4[tid];
    dst[256] = sy4[tid + 256];
}

// ---------------------------------------------------------------------------
// K4: broadcast h=0 slice (4 MB) to h = 1..63 (252 MB of streaming writes).
// 256 blocks, 16 KB segment in 4 registers per thread, 63*4 independent
// plain STG.128 per thread (plain stores measured faster than __stcs).
// ---------------------------------------------------------------------------
__global__ void __launch_bounds__(256) k_bcast(float* __restrict__ out) {
    const int tid = threadIdx.x;
    const size_t segOff4 = (size_t)blockIdx.x * 1024;  // float4 units (16KB/block)
    const float4* src = (const float4*)out + segOff4;
    float4 v0 = src[tid];
    float4 v1 = src[tid + 256];
    float4 v2 = src[tid + 512];
    float4 v3 = src[tid + 768];
    float4* dst = (float4*)out + segOff4 + tid;
    const size_t hstride4 = (size_t)NB * LQ * EE / 4;  // 262144 float4 = 4 MB
#pragma unroll 7
    for (int h = 1; h < HH; h++) {
        float4* p = dst + (size_t)h * hstride4;
        p[0] = v0;
        p[256] = v1;
        p[512] = v2;
        p[768] = v3;
    }
}

// ---------------------------------------------------------------------------
extern "C" void kernel_launch(void* const* d_in, const int* in_sizes, int n_in,
                              void* d_out, int out_size) {
    const float* values = (const float*)d_in[0];
    const float* keys   = (const float*)d_in[1];
    const float* query  = (const float*)d_in[2];
    const float* W      = (const float*)d_in[3];
    const float* b      = (const float*)d_in[4];
    const float* lnw    = (const float*)d_in[5];
    const float* lnb    = (const float*)d_in[6];
    float* out = (float*)d_out;

    k_front<<<384, 256>>>(values, query, keys);
    k_M<<<64, 256>>>(W);
    k_compute<<<512, 256>>>(b, lnw, lnb, out);
    k_bcast<<<256, 256>>>(out);
}

// round 13
// speedup vs baseline: 1.0087x; 1.0087x over previous
#include <cuda_runtime.h>

#define NB 64
#define LQ 256
#define EE 64
#define HH 64

// Scratch (static __device__ — no allocations allowed)
__device__ float g_vt[NB * LQ * EE];    // vt[n][l][k] = values[k][l][n]   (4 MB)
__device__ float g_M[NB * EE * EE];     // M[n][e][k] = (W @ A_n)[e][k]    (1 MB)

// ---------------------------------------------------------------------------
// K_front: merged launch.
//   blocks [0,64):   per-n: energy Q·K^T -> softmax (in smem) -> M_n = W@A_n
//   blocks [64,320): transpose values[k][l][n] -> vt[n][l][k]  (one per l)
// Smem pool (floats): sE [0,4352) | sQ [4352,6400) | sK [6400,8448)
//                     sWt aliases [4352,8704) in the M phase.
// ---------------------------------------------------------------------------
__global__ void __launch_bounds__(256) k_front(const float* __restrict__ values,
                                               const float* __restrict__ query,
                                               const float* __restrict__ keys,
                                               const float* __restrict__ W) {
    __shared__ float sh[8704];           // 34.8 KB pool
    const int tid = threadIdx.x;

    if (blockIdx.x >= 64) {
        // ---- transpose phase ----
        float (*tile)[65] = (float(*)[65])sh;
        const int l = blockIdx.x - 64;
#pragma unroll
        for (int i = 0; i < 4; i++) {
            int f = i * 256 + tid;          // float4 index 0..1023
            int k = f >> 4;                 // 0..63
            int n4 = f & 15;                // 0..15
            float4 v = *(const float4*)(values + ((k * LQ + l) * EE) + n4 * 4);
            tile[k][n4 * 4 + 0] = v.x;
            tile[k][n4 * 4 + 1] = v.y;
            tile[k][n4 * 4 + 2] = v.z;
            tile[k][n4 * 4 + 3] = v.w;
        }
        __syncthreads();
#pragma unroll
        for (int i = 0; i < 4; i++) {
            int f = i * 256 + tid;
            int nn = f >> 4;
            int k4 = f & 15;
            float4 v = make_float4(tile[k4 * 4 + 0][nn], tile[k4 * 4 + 1][nn],
                                   tile[k4 * 4 + 2][nn], tile[k4 * 4 + 3][nn]);
            *(float4*)(g_vt + ((nn * LQ + l) * EE) + k4 * 4) = v;
        }
        return;
    }

    // ---- attention + M phase (one block per n) ----
    const int n = blockIdx.x;
    float (*sE)[68] = (float(*)[68])sh;            // [a][b] energy/attn, 4352 f
    float (*sQ)[64] = (float(*)[64])(sh + 4352);   // [l'][a]  2048 f
    float (*sK)[64] = (float(*)[64])(sh + 6400);   // [l'][b]  2048 f
    float (*sWt)[68] = (float(*)[68])(sh + 4352);  // [e'][e]  aliases sQ/sK

    const int a0 = (tid >> 4) * 4;   // 0..60
    const int b0 = (tid & 15) * 4;   // 0..60

    // load slots: each thread loads rows lrow and lrow+16 of the 32-row chunk
    const int lrow = tid >> 4;       // 0..15
    const int c4 = (tid & 15) * 4;   // float col 0..60

    float acc[4][4] = {};

    // prefetch chunk 0
    const float* qb = query + n * LQ * EE;
    const float* kb = keys + n * LQ * EE;
    float4 q0 = *(const float4*)(qb + lrow * EE + c4);
    float4 q1 = *(const float4*)(qb + (16 + lrow) * EE + c4);
    float4 k0 = *(const float4*)(kb + lrow * EE + c4);
    float4 k1 = *(const float4*)(kb + (16 + lrow) * EE + c4);

    for (int c = 0; c < 8; c++) {
        *(float4*)&sQ[lrow][c4] = q0;
        *(float4*)&sQ[16 + lrow][c4] = q1;
        *(float4*)&sK[lrow][c4] = k0;
        *(float4*)&sK[16 + lrow][c4] = k1;
        __syncthreads();

        if (c < 7) {
            const int l0 = (c + 1) * 32;
            q0 = *(const float4*)(qb + (l0 + lrow) * EE + c4);
            q1 = *(const float4*)(qb + (l0 + 16 + lrow) * EE + c4);
            k0 = *(const float4*)(kb + (l0 + lrow) * EE + c4);
            k1 = *(const float4*)(kb + (l0 + 16 + lrow) * EE + c4);
        }

#pragma unroll
        for (int lp = 0; lp < 32; lp++) {
            float4 qv = *(const float4*)&sQ[lp][a0];
            float4 kv = *(const float4*)&sK[lp][b0];
            acc[0][0] += qv.x * kv.x; acc[0][1] += qv.x * kv.y; acc[0][2] += qv.x * kv.z; acc[0][3] += qv.x * kv.w;
            acc[1][0] += qv.y * kv.x; acc[1][1] += qv.y * kv.y; acc[1][2] += qv.y * kv.z; acc[1][3] += qv.y * kv.w;
            acc[2][0] += qv.z * kv.x; acc[2][1] += qv.z * kv.y; acc[2][2] += qv.z * kv.z; acc[2][3] += qv.z * kv.w;
            acc[3][0] += qv.w * kv.x; acc[3][1] += qv.w * kv.y; acc[3][2] += qv.w * kv.z; acc[3][3] += qv.w * kv.w;
        }
        __syncthreads();
    }
#pragma unroll
    for (int i = 0; i < 4; i++)
        *(float4*)&sE[a0 + i][b0] = make_float4(acc[i][0], acc[i][1], acc[i][2], acc[i][3]);
    __syncthreads();

    // ---- softmax in place: 8 warps x 8 rows; hd=1 so no scale ----
    const int w = tid >> 5, lane = tid & 31;
#pragma unroll
    for (int r = 0; r < 8; r++) {
        int row = w * 8 + r;
        float v0 = sE[row][lane];
        float v1 = sE[row][lane + 32];
        float m = fmaxf(v0, v1);
#pragma unroll
        for (int off = 16; off; off >>= 1) m = fmaxf(m, __shfl_xor_sync(0xffffffffu, m, off));
        float e0 = __expf(v0 - m);
        float e1 = __expf(v1 - m);
        float s = e0 + e1;
#pragma unroll
        for (int off = 16; off; off >>= 1) s += __shfl_xor_sync(0xffffffffu, s, off);
        float inv = 1.0f / s;
        sE[row][lane] = e0 * inv;
        sE[row][lane + 32] = e1 * inv;
    }
    __syncthreads();

    // ---- load W^T into the aliased region (Q/K dead now) ----
#pragma unroll
    for (int i = 0; i < 16; i++) {
        int idx = i * 256 + tid;
        sWt[idx & 63][idx >> 6] = W[idx];    // sWt[e'][e] = W[e][e']
    }
    __syncthreads();

    // ---- M_n[e][k] = sum_e' W[e][e'] * attn[e'][k] ----
    {
        const int e0 = (tid >> 4) * 4;
        const int k0 = (tid & 15) * 4;
        float m00=0.f,m01=0.f,m02=0.f,m03=0.f;
        float m10=0.f,m11=0.f,m12=0.f,m13=0.f;
        float m20=0.f,m21=0.f,m22=0.f,m23=0.f;
        float m30=0.f,m31=0.f,m32=0.f,m33=0.f;
#pragma unroll
        for (int ep = 0; ep < 64; ep++) {
            float4 wv = *(const float4*)&sWt[ep][e0];
            float4 av = *(const float4*)&sE[ep][k0];
            m00 += wv.x * av.x; m01 += wv.x * av.y; m02 += wv.x * av.z; m03 += wv.x * av.w;
            m10 += wv.y * av.x; m11 += wv.y * av.y; m12 += wv.y * av.z; m13 += wv.y * av.w;
            m20 += wv.z * av.x; m21 += wv.z * av.y; m22 += wv.z * av.z; m23 += wv.z * av.w;
            m30 += wv.w * av.x; m31 += wv.w * av.y; m32 += wv.w * av.z; m33 += wv.w * av.w;
        }
        float* Mo = g_M + n * 4096;
        *(float4*)(Mo + (e0 + 0) * 64 + k0) = make_float4(m00, m01, m02, m03);
        *(float4*)(Mo + (e0 + 1) * 64 + k0) = make_float4(m10, m11, m12, m13);
        *(float4*)(Mo + (e0 + 2) * 64 + k0) = make_float4(m20, m21, m22, m23);
        *(float4*)(Mo + (e0 + 3) * 64 + k0) = make_float4(m30, m31, m32, m33);
    }
}

// ---------------------------------------------------------------------------
// K3: tiled GEMV + LayerNorm; writes ONLY the h=0 slice (4 MB).
// grid: 512 blocks = (n, 32-l chunk); 256 threads = (16 l-pairs) x (16 e-quads)
// ---------------------------------------------------------------------------
__global__ void __launch_bounds__(256) k_compute(const float* __restrict__ bias,
                                                 const float* __restrict__ lnw,
                                                 const float* __restrict__ lnb,
                                                 float* __restrict__ out) {
    const int n = blockIdx.x >> 3;
    const int lc = blockIdx.x & 7;
    const int tid = threadIdx.x;

    __shared__ float sMt[64][68];   // sMt[k][e] = M_n[e][k]
    __shared__ float sv[32][68];    // sv[l'][k]
    __shared__ float sy[32][64];    // normalized output tile
    __shared__ float sb[64], sw[64], sbeta[64];

    if (tid < 64) {
        sb[tid] = bias[tid];
        sw[tid] = lnw[tid];
        sbeta[tid] = lnb[tid];
    }

    // Load + transpose M_n (64x64) into sMt[k][e]
    const float* Mn = g_M + n * 4096;
#pragma unroll
    for (int i = 0; i < 16; i++) {
        int idx = i * 256 + tid;
        int e = idx >> 6, k = idx & 63;
        sMt[k][e] = Mn[idx];
    }
    // Load vt tile (32 x 64), coalesced
    const int lbase = lc * 32;
    const float* vtn = g_vt + (n * LQ + lbase) * EE;
#pragma unroll
    for (int i = 0; i < 8; i++) {
        int idx = i * 256 + tid;
        sv[idx >> 6][idx & 63] = vtn[idx];
    }
    __syncthreads();

    // Micro-tile: 2 l-rows x 4 e-cols per thread
    const int r0 = (tid >> 4) * 2;   // 0..30
    const int e0 = (tid & 15) * 4;   // 0..60

    float a00 = 0.f, a01 = 0.f, a02 = 0.f, a03 = 0.f;
    float a10 = 0.f, a11 = 0.f, a12 = 0.f, a13 = 0.f;
#pragma unroll
    for (int k = 0; k < 64; k++) {
        float v0 = sv[r0][k];
        float v1 = sv[r0 + 1][k];
        float4 m = *(const float4*)&sMt[k][e0];
        a00 += v0 * m.x; a01 += v0 * m.y; a02 += v0 * m.z; a03 += v0 * m.w;
        a10 += v1 * m.x; a11 += v1 * m.y; a12 += v1 * m.z; a13 += v1 * m.w;
    }
    // add fc bias before LN
    float b0v = sb[e0], b1v = sb[e0 + 1], b2v = sb[e0 + 2], b3v = sb[e0 + 3];
    a00 += b0v; a01 += b1v; a02 += b2v; a03 += b3v;
    a10 += b0v; a11 += b1v; a12 += b2v; a13 += b3v;

    // LN stats: reduce over the 16 lanes that share a row-pair (offsets 1..8)
    float s0 = (a00 + a01) + (a02 + a03);
    float q0 = (a00 * a00 + a01 * a01) + (a02 * a02 + a03 * a03);
    float s1 = (a10 + a11) + (a12 + a13);
    float q1 = (a10 * a10 + a11 * a11) + (a12 * a12 + a13 * a13);
#pragma unroll
    for (int off = 8; off; off >>= 1) {
        s0 += __shfl_xor_sync(0xffffffffu, s0, off);
        q0 += __shfl_xor_sync(0xffffffffu, q0, off);
        s1 += __shfl_xor_sync(0xffffffffu, s1, off);
        q1 += __shfl_xor_sync(0xffffffffu, q1, off);
    }
    float mu0 = s0 * (1.0f / 64.0f);
    float var0 = q0 * (1.0f / 64.0f) - mu0 * mu0;
    float ri0 = rsqrtf(var0 + 1e-5f);
    float mu1 = s1 * (1.0f / 64.0f);
    float var1 = q1 * (1.0f / 64.0f) - mu1 * mu1;
    float ri1 = rsqrtf(var1 + 1e-5f);

    float w0 = sw[e0], w1 = sw[e0 + 1], w2 = sw[e0 + 2], w3 = sw[e0 + 3];
    float g0 = sbeta[e0], g1 = sbeta[e0 + 1], g2 = sbeta[e0 + 2], g3 = sbeta[e0 + 3];

    *(float4*)&sy[r0][e0] = make_float4((a00 - mu0) * ri0 * w0 + g0,
                                        (a01 - mu0) * ri0 * w1 + g1,
                                        (a02 - mu0) * ri0 * w2 + g2,
                                        (a03 - mu0) * ri0 * w3 + g3);
    *(float4*)&sy[r0 + 1][e0] = make_float4((a10 - mu1) * ri1 * w0 + g0,
                                            (a11 - mu1) * ri1 * w1 + g1,
                                            (a12 - mu1) * ri1 * w2 + g2,
                                            (a13 - mu1) * ri1 * w3 + g3);
    __syncthreads();

    // write h = 0 slice only (coalesced STG.128)
    const float4* sy4 = (const float4*)sy;
    float4* dst = (float4*)out + n * 4096 + lc * 512 + tid;
    dst[0] = sy4[tid];
    dst[256] = sy4[tid + 256];
}

// ---------------------------------------------------------------------------
// K4: broadcast h=0 slice (4 MB) to h = 1..63 (252 MB of streaming writes).
// 256 blocks, 16 KB segment in 4 registers per thread, 63*4 independent
// plain STG.128 per thread (plain stores measured faster than __stcs).
// ---------------------------------------------------------------------------
__global__ void __launch_bounds__(256) k_bcast(float* __restrict__ out) {
    const int tid = threadIdx.x;
    const size_t segOff4 = (size_t)blockIdx.x * 1024;  // float4 units (16KB/block)
    const float4* src = (const float4*)out + segOff4;
    float4 v0 = src[tid];
    float4 v1 = src[tid + 256];
    float4 v2 = src[tid + 512];
    float4 v3 = src[tid + 768];
    float4* dst = (float4*)out + segOff4 + tid;
    const size_t hstride4 = (size_t)NB * LQ * EE / 4;  // 262144 float4 = 4 MB
#pragma unroll 7
    for (int h = 1; h < HH; h++) {
        float4* p = dst + (size_t)h * hstride4;
        p[0] = v0;
        p[256] = v1;
        p[512] = v2;
        p[768] = v3;
    }
}

// ---------------------------------------------------------------------------
extern "C" void kernel_launch(void* const* d_in, const int* in_sizes, int n_in,
                              void* d_out, int out_size) {
    const float* values = (const float*)d_in[0];
    const float* keys   = (const float*)d_in[1];
    const float* query  = (const float*)d_in[2];
    const float* W      = (const float*)d_in[3];
    const float* b      = (const float*)d_in[4];
    const float* lnw    = (const float*)d_in[5];
    const float* lnb    = (const float*)d_in[6];
    float* out = (float*)d_out;

    k_front<<<320, 256>>>(values, query, keys, W);
    k_compute<<<512, 256>>>(b, lnw, lnb, out);
    k_bcast<<<256, 256>>>(out);
}